// round 5
// baseline (speedup 1.0000x reference)
#include <cuda_runtime.h>

#define NN 50000
#define EE 1600000
#define CC 128
#define C4 (CC/4)
#define NG 128

// ---- scratch (static device globals) ----
__device__ float4 s_H [NN * C4];     // h = act(A) @ W
__device__ float4 s_P0[NN * C4];     // ping
__device__ float4 s_P1[NN * C4];     // pong
__device__ float  s_dinv[NN];
__device__ int    s_deg [NN];
__device__ int    s_rowptr[NN + 1];
__device__ int    s_cursor[NN];
__device__ int    s_csrc [EE];
__device__ float  s_coef [EE];

// ============ prologue ============
__global__ void zero_deg_k() {
    int i = blockIdx.x * blockDim.x + threadIdx.x;
    if (i < NN) s_deg[i] = 0;
}

// edge_index is int32 [2, E]: src = ei[e], dst = ei[E + e]
__global__ void deg_k(const int* __restrict__ ei) {
    int e = blockIdx.x * blockDim.x + threadIdx.x;
    if (e < EE) {
        int dst = ei[EE + e];
        dst = min(max(dst, 0), NN - 1);          // safety clamp
        atomicAdd(&s_deg[dst], 1);
    }
}

__global__ void dinv_k() {
    int i = blockIdx.x * blockDim.x + threadIdx.x;
    if (i < NN) s_dinv[i] = rsqrtf((float)s_deg[i] + 1.0f);
}

// exclusive scan of degrees -> rowptr, cursor (single block, Hillis-Steele)
__global__ void scan_k() {
    __shared__ int sh[1024];
    const int tid = threadIdx.x;
    int carry = 0;
    for (int base = 0; base < NN; base += 1024) {
        int i = base + tid;
        int v = (i < NN) ? s_deg[i] : 0;
        sh[tid] = v;
        __syncthreads();
        for (int off = 1; off < 1024; off <<= 1) {
            int t = (tid >= off) ? sh[tid - off] : 0;
            __syncthreads();
            sh[tid] += t;
            __syncthreads();
        }
        if (i < NN) {
            int ex = carry + sh[tid] - v;
            s_rowptr[i] = ex;
            s_cursor[i] = ex;
        }
        carry += sh[1023];
        __syncthreads();
    }
    if (tid == 0) s_rowptr[NN] = EE;
}

// counting-sort: group edges by dst, precompute coef = dinv[src]*dinv[dst]
__global__ void build_k(const int* __restrict__ ei) {
    int e = blockIdx.x * blockDim.x + threadIdx.x;
    if (e >= EE) return;
    int src = ei[e];
    int dst = ei[EE + e];
    src = min(max(src, 0), NN - 1);              // safety clamp
    dst = min(max(dst, 0), NN - 1);
    int slot = atomicAdd(&s_cursor[dst], 1);
    slot = min(max(slot, 0), EE - 1);
    s_csrc[slot] = src;
    s_coef[slot] = s_dinv[src] * s_dinv[dst];
}

// ============ GEMM: H = act(A) @ W ============
// SRC: 0 = external x (no relu), 1 = s_P0 (relu), 2 = s_P1 (relu)
// 128 threads = one output column each; 32 rows per block.
template<int SRC>
__global__ void gemm_k(const float* __restrict__ Aext, const float* __restrict__ W) {
    __shared__ float sA[32 * CC];
    const float* A = (SRC == 0) ? Aext
                   : (SRC == 1) ? (const float*)s_P0 : (const float*)s_P1;
    float* H = (float*)s_H;

    const int row0 = blockIdx.x * 32;
    const int col  = threadIdx.x;

    #pragma unroll
    for (int r = 0; r < 32; r++) {
        int row = row0 + r;
        float v = (row < NN) ? A[(size_t)row * CC + col] : 0.f;
        if (SRC != 0) v = fmaxf(v, 0.f);
        sA[r * CC + col] = v;
    }
    __syncthreads();

    float acc[32];
    #pragma unroll
    for (int r = 0; r < 32; r++) acc[r] = 0.f;

    const float4* sA4 = (const float4*)sA;
    for (int k4 = 0; k4 < 32; k4++) {
        float w0 = W[(4 * k4 + 0) * CC + col];
        float w1 = W[(4 * k4 + 1) * CC + col];
        float w2 = W[(4 * k4 + 2) * CC + col];
        float w3 = W[(4 * k4 + 3) * CC + col];
        #pragma unroll
        for (int r = 0; r < 32; r++) {
            float4 a = sA4[r * 32 + k4];          // broadcast LDS.128
            acc[r] = fmaf(a.x, w0, acc[r]);
            acc[r] = fmaf(a.y, w1, acc[r]);
            acc[r] = fmaf(a.z, w2, acc[r]);
            acc[r] = fmaf(a.w, w3, acc[r]);
        }
    }

    #pragma unroll
    for (int r = 0; r < 32; r++) {
        int row = row0 + r;
        if (row < NN) H[(size_t)row * CC + col] = acc[r];
    }
}

// ============ aggregation (pure gather, no atomics) ============
// OUT[i] = sum_e H[src_e]*coef_e + H[i]*dinv[i]^2 + b
// one warp per node; lane covers 4 channels
template<int DST>
__global__ void agg_k(const float* __restrict__ b) {
    int node = blockIdx.x * 8 + (threadIdx.x >> 5);
    int lane = threadIdx.x & 31;
    if (node >= NN) return;
    float4* OUT = (DST == 0) ? s_P0 : s_P1;

    float di = s_dinv[node];
    float sc = di * di;
    float4 h = s_H[(size_t)node * C4 + lane];
    float4 acc;
    acc.x = fmaf(h.x, sc, b[lane * 4 + 0]);
    acc.y = fmaf(h.y, sc, b[lane * 4 + 1]);
    acc.z = fmaf(h.z, sc, b[lane * 4 + 2]);
    acc.w = fmaf(h.w, sc, b[lane * 4 + 3]);

    const int beg = s_rowptr[node];
    const int end = s_rowptr[node + 1];
    int e = beg;
    for (; e + 2 <= end; e += 2) {
        int   i0 = s_csrc[e],  i1 = s_csrc[e + 1];
        float c0 = s_coef[e],  c1 = s_coef[e + 1];
        float4 v0 = s_H[(size_t)i0 * C4 + lane];
        float4 v1 = s_H[(size_t)i1 * C4 + lane];
        acc.x = fmaf(v0.x, c0, fmaf(v1.x, c1, acc.x));
        acc.y = fmaf(v0.y, c0, fmaf(v1.y, c1, acc.y));
        acc.z = fmaf(v0.z, c0, fmaf(v1.z, c1, acc.z));
        acc.w = fmaf(v0.w, c0, fmaf(v1.w, c1, acc.w));
    }
    if (e < end) {
        float4 v0 = s_H[(size_t)s_csrc[e] * C4 + lane];
        float c0 = s_coef[e];
        acc.x = fmaf(v0.x, c0, acc.x);
        acc.y = fmaf(v0.y, c0, acc.y);
        acc.z = fmaf(v0.z, c0, acc.z);
        acc.w = fmaf(v0.w, c0, acc.w);
    }
    OUT[(size_t)node * C4 + lane] = acc;
}

// ============ fused mean-pool (batch sorted int32) + FC ============
__global__ void poolfc_k(const int* __restrict__ batch,
                         const float* __restrict__ Wfc,
                         const float* __restrict__ bfc,
                         float* __restrict__ out) {
    int g = blockIdx.x;
    int t = threadIdx.x;
    __shared__ int sb[2];
    if (t < 2) {
        int key = g + t;
        int lo = 0, hi = NN;
        while (lo < hi) {
            int mid = (lo + hi) >> 1;
            if (batch[mid] < key) lo = mid + 1; else hi = mid;
        }
        sb[t] = lo;
    }
    __syncthreads();
    const int beg = sb[0], end = sb[1];

    const float* A = (const float*)s_P1;   // final layer output (pre-relu)
    float s = 0.f;
    for (int r = beg; r < end; r++)
        s += fmaxf(A[(size_t)r * CC + t], 0.f);

    float v = s * Wfc[t];
    #pragma unroll
    for (int o = 16; o; o >>= 1) v += __shfl_xor_sync(0xffffffffu, v, o);
    __shared__ float sred[4];
    if ((t & 31) == 0) sred[t >> 5] = v;
    __syncthreads();
    if (t == 0) {
        float total = sred[0] + sred[1] + sred[2] + sred[3];
        out[g] = total / fmaxf((float)(end - beg), 1.0f) + bfc[0];
    }
}

extern "C" void kernel_launch(void* const* d_in, const int* in_sizes, int n_in,
                              void* d_out, int out_size) {
    const float* x   = (const float*)d_in[0];
    const int*   ei  = (const int*)d_in[1];    // int32 [2, E] (JAX x64 disabled)
    const int*   bat = (const int*)d_in[2];    // int32 [N]
    const float* W1  = (const float*)d_in[3];
    const float* b1  = (const float*)d_in[4];
    const float* W2  = (const float*)d_in[5];
    const float* b2  = (const float*)d_in[6];
    const float* Wfc = (const float*)d_in[7];
    const float* bfc = (const float*)d_in[8];
    float*       out = (float*)d_out;

    const int T = 256;
    const int NB_N = (NN + T - 1) / T;
    const int NB_E = (EE + T - 1) / T;
    const int GB   = (NN + 31) / 32;
    const int AB   = (NN + 7) / 8;

    // prologue: CSR build (int atomics only)
    zero_deg_k<<<NB_N, T>>>();
    deg_k     <<<NB_E, T>>>(ei);
    dinv_k    <<<NB_N, T>>>();
    scan_k    <<<1, 1024>>>();
    build_k   <<<NB_E, T>>>(ei);

    // 4 GCN layers: gemm -> gather-agg (ping/pong via templates)
    gemm_k<0><<<GB, CC>>>(x, W1);  agg_k<0><<<AB, T>>>(b1);   // x  -> P0
    gemm_k<1><<<GB, CC>>>(x, W2);  agg_k<1><<<AB, T>>>(b2);   // P0 -> P1
    gemm_k<2><<<GB, CC>>>(x, W2);  agg_k<0><<<AB, T>>>(b2);   // P1 -> P0
    gemm_k<1><<<GB, CC>>>(x, W2);  agg_k<1><<<AB, T>>>(b2);   // P0 -> P1

    // pool (relu fused) + fc
    poolfc_k<<<NG, CC>>>(bat, Wfc, bfc, out);
}

// round 6
// speedup vs baseline: 1.1141x; 1.1141x over previous
#include <cuda_runtime.h>

#define NN 50000
#define EE 1600000
#define CC 128
#define C4 (CC/4)
#define NG 128
#define SB 1024                 // scan block size
#define NB ((NN + SB - 1) / SB) // 49 scan blocks

// ---- scratch (static device globals) ----
__device__ float4 s_H [NN * C4];     // h = act(A) @ W
__device__ float4 s_P0[NN * C4];     // ping
__device__ float4 s_P1[NN * C4];     // pong
__device__ float  s_dinv[NN];
__device__ int    s_deg [NN];
__device__ int    s_rowptr[NN + 1];
__device__ int    s_cursor[NN];
__device__ int    s_csrc [EE];
__device__ float  s_coef [EE];
__device__ int    s_bsum[64];
__device__ int    s_boff[64];

// ============ prologue ============
__global__ void zero_deg_k() {
    int i = blockIdx.x * blockDim.x + threadIdx.x;
    if (i < NN) s_deg[i] = 0;
}

// edge_index int32 [2, E]: src = ei[e], dst = ei[E + e]
__global__ void deg_k(const int* __restrict__ ei) {
    int e = blockIdx.x * blockDim.x + threadIdx.x;
    if (e < EE) {
        int dst = ei[EE + e];
        dst = min(max(dst, 0), NN - 1);
        atomicAdd(&s_deg[dst], 1);
    }
}

// ---- hierarchical exclusive scan of s_deg -> s_rowptr ----
// phase 1: per-block warp-shuffle scan; block-exclusive into rowptr, totals to bsum
__global__ void scan1_k() {
    const int tid  = threadIdx.x;
    const int lane = tid & 31;
    const int wid  = tid >> 5;
    const int i    = blockIdx.x * SB + tid;
    int v = (i < NN) ? s_deg[i] : 0;

    int x = v;
    #pragma unroll
    for (int o = 1; o < 32; o <<= 1) {
        int t = __shfl_up_sync(0xffffffffu, x, o);
        if (lane >= o) x += t;
    }
    __shared__ int wsum[32];
    if (lane == 31) wsum[wid] = x;
    __syncthreads();
    if (wid == 0) {
        int s = wsum[lane];
        #pragma unroll
        for (int o = 1; o < 32; o <<= 1) {
            int t = __shfl_up_sync(0xffffffffu, s, o);
            if (lane >= o) s += t;
        }
        wsum[lane] = s;
    }
    __syncthreads();
    int incl = x + (wid ? wsum[wid - 1] : 0);
    if (i < NN) s_rowptr[i] = incl - v;            // block-local exclusive
    if (tid == SB - 1) s_bsum[blockIdx.x] = incl;  // block total
}

// phase 2: scan the 49 block totals (one tiny block)
__global__ void scan2_k() {
    __shared__ int sh[64];
    int t = threadIdx.x;
    int v = (t < NB) ? s_bsum[t] : 0;
    sh[t] = v;
    __syncthreads();
    for (int o = 1; o < 64; o <<= 1) {
        int u = (t >= o) ? sh[t - o] : 0;
        __syncthreads();
        sh[t] += u;
        __syncthreads();
    }
    s_boff[t] = sh[t] - v;                          // exclusive block offset
}

// phase 3: apply offsets; init cursor; compute dinv; set sentinel
__global__ void scan3_k() {
    int i = blockIdx.x * SB + threadIdx.x;
    if (i < NN) {
        int ex = s_rowptr[i] + s_boff[blockIdx.x];
        s_rowptr[i] = ex;
        s_cursor[i] = ex;
        s_dinv[i]   = rsqrtf((float)s_deg[i] + 1.0f);
    }
    if (i == 0) s_rowptr[NN] = EE;
}

// counting-sort: group edges by dst, precompute coef = dinv[src]*dinv[dst]
__global__ void build_k(const int* __restrict__ ei) {
    int e = blockIdx.x * blockDim.x + threadIdx.x;
    if (e >= EE) return;
    int src = ei[e];
    int dst = ei[EE + e];
    src = min(max(src, 0), NN - 1);
    dst = min(max(dst, 0), NN - 1);
    int slot = atomicAdd(&s_cursor[dst], 1);
    slot = min(max(slot, 0), EE - 1);
    s_csrc[slot] = src;
    s_coef[slot] = s_dinv[src] * s_dinv[dst];
}

// ============ GEMM: H = act(A) @ W ============
// SRC: 0 = external x (no relu), 1 = s_P0 (relu), 2 = s_P1 (relu)
template<int SRC>
__global__ void gemm_k(const float* __restrict__ Aext, const float* __restrict__ W) {
    __shared__ float sA[32 * CC];
    const float* A = (SRC == 0) ? Aext
                   : (SRC == 1) ? (const float*)s_P0 : (const float*)s_P1;
    float* H = (float*)s_H;

    const int row0 = blockIdx.x * 32;
    const int col  = threadIdx.x;

    #pragma unroll
    for (int r = 0; r < 32; r++) {
        int row = row0 + r;
        float v = (row < NN) ? A[(size_t)row * CC + col] : 0.f;
        if (SRC != 0) v = fmaxf(v, 0.f);
        sA[r * CC + col] = v;
    }
    __syncthreads();

    float acc[32];
    #pragma unroll
    for (int r = 0; r < 32; r++) acc[r] = 0.f;

    const float4* sA4 = (const float4*)sA;
    for (int k4 = 0; k4 < 32; k4++) {
        float w0 = W[(4 * k4 + 0) * CC + col];
        float w1 = W[(4 * k4 + 1) * CC + col];
        float w2 = W[(4 * k4 + 2) * CC + col];
        float w3 = W[(4 * k4 + 3) * CC + col];
        #pragma unroll
        for (int r = 0; r < 32; r++) {
            float4 a = sA4[r * 32 + k4];          // broadcast LDS.128
            acc[r] = fmaf(a.x, w0, acc[r]);
            acc[r] = fmaf(a.y, w1, acc[r]);
            acc[r] = fmaf(a.z, w2, acc[r]);
            acc[r] = fmaf(a.w, w3, acc[r]);
        }
    }

    #pragma unroll
    for (int r = 0; r < 32; r++) {
        int row = row0 + r;
        if (row < NN) H[(size_t)row * CC + col] = acc[r];
    }
}

// ============ aggregation (pure gather, no atomics) ============
template<int DST>
__global__ void agg_k(const float* __restrict__ b) {
    int node = blockIdx.x * 8 + (threadIdx.x >> 5);
    int lane = threadIdx.x & 31;
    if (node >= NN) return;
    float4* OUT = (DST == 0) ? s_P0 : s_P1;

    float di = s_dinv[node];
    float sc = di * di;
    float4 h = s_H[(size_t)node * C4 + lane];
    float4 acc;
    acc.x = fmaf(h.x, sc, b[lane * 4 + 0]);
    acc.y = fmaf(h.y, sc, b[lane * 4 + 1]);
    acc.z = fmaf(h.z, sc, b[lane * 4 + 2]);
    acc.w = fmaf(h.w, sc, b[lane * 4 + 3]);

    const int beg = s_rowptr[node];
    const int end = s_rowptr[node + 1];
    int e = beg;
    for (; e + 2 <= end; e += 2) {
        int   i0 = s_csrc[e],  i1 = s_csrc[e + 1];
        float c0 = s_coef[e],  c1 = s_coef[e + 1];
        float4 v0 = s_H[(size_t)i0 * C4 + lane];
        float4 v1 = s_H[(size_t)i1 * C4 + lane];
        acc.x = fmaf(v0.x, c0, fmaf(v1.x, c1, acc.x));
        acc.y = fmaf(v0.y, c0, fmaf(v1.y, c1, acc.y));
        acc.z = fmaf(v0.z, c0, fmaf(v1.z, c1, acc.z));
        acc.w = fmaf(v0.w, c0, fmaf(v1.w, c1, acc.w));
    }
    if (e < end) {
        float4 v0 = s_H[(size_t)s_csrc[e] * C4 + lane];
        float c0 = s_coef[e];
        acc.x = fmaf(v0.x, c0, acc.x);
        acc.y = fmaf(v0.y, c0, acc.y);
        acc.z = fmaf(v0.z, c0, acc.z);
        acc.w = fmaf(v0.w, c0, acc.w);
    }
    OUT[(size_t)node * C4 + lane] = acc;
}

// ============ fused mean-pool (batch sorted int32) + FC ============
__global__ void poolfc_k(const int* __restrict__ batch,
                         const float* __restrict__ Wfc,
                         const float* __restrict__ bfc,
                         float* __restrict__ out) {
    int g = blockIdx.x;
    int t = threadIdx.x;
    __shared__ int sb[2];
    if (t < 2) {
        int key = g + t;
        int lo = 0, hi = NN;
        while (lo < hi) {
            int mid = (lo + hi) >> 1;
            if (batch[mid] < key) lo = mid + 1; else hi = mid;
        }
        sb[t] = lo;
    }
    __syncthreads();
    const int beg = sb[0], end = sb[1];

    const float* A = (const float*)s_P1;
    float s = 0.f;
    for (int r = beg; r < end; r++)
        s += fmaxf(A[(size_t)r * CC + t], 0.f);

    float v = s * Wfc[t];
    #pragma unroll
    for (int o = 16; o; o >>= 1) v += __shfl_xor_sync(0xffffffffu, v, o);
    __shared__ float sred[4];
    if ((t & 31) == 0) sred[t >> 5] = v;
    __syncthreads();
    if (t == 0) {
        float total = sred[0] + sred[1] + sred[2] + sred[3];
        out[g] = total / fmaxf((float)(end - beg), 1.0f) + bfc[0];
    }
}

extern "C" void kernel_launch(void* const* d_in, const int* in_sizes, int n_in,
                              void* d_out, int out_size) {
    const float* x   = (const float*)d_in[0];
    const int*   ei  = (const int*)d_in[1];    // int32 [2, E]
    const int*   bat = (const int*)d_in[2];    // int32 [N]
    const float* W1  = (const float*)d_in[3];
    const float* b1  = (const float*)d_in[4];
    const float* W2  = (const float*)d_in[5];
    const float* b2  = (const float*)d_in[6];
    const float* Wfc = (const float*)d_in[7];
    const float* bfc = (const float*)d_in[8];
    float*       out = (float*)d_out;

    const int T = 256;
    const int NB_N = (NN + T - 1) / T;
    const int NB_E = (EE + T - 1) / T;
    const int GB   = (NN + 31) / 32;
    const int AB   = (NN + 7) / 8;

    // prologue: CSR build (int atomics + hierarchical scan)
    zero_deg_k<<<NB_N, T>>>();
    deg_k     <<<NB_E, T>>>(ei);
    scan1_k   <<<NB, SB>>>();
    scan2_k   <<<1, 64>>>();
    scan3_k   <<<NB, SB>>>();
    build_k   <<<NB_E, T>>>(ei);

    // 4 GCN layers: gemm -> gather-agg
    gemm_k<0><<<GB, CC>>>(x, W1);  agg_k<0><<<AB, T>>>(b1);   // x  -> P0
    gemm_k<1><<<GB, CC>>>(x, W2);  agg_k<1><<<AB, T>>>(b2);   // P0 -> P1
    gemm_k<2><<<GB, CC>>>(x, W2);  agg_k<0><<<AB, T>>>(b2);   // P1 -> P0
    gemm_k<1><<<GB, CC>>>(x, W2);  agg_k<1><<<AB, T>>>(b2);   // P0 -> P1

    // pool (relu fused) + fc
    poolfc_k<<<NG, CC>>>(bat, Wfc, bfc, out);
}

// round 7
// speedup vs baseline: 1.2113x; 1.0873x over previous
#include <cuda_runtime.h>
#include <cuda_fp16.h>

#define NN 50000
#define EE 1600000
#define CC 128
#define C4 (CC/4)
#define NG 128
#define SB 1024                 // scan block size
#define NBK ((NN + SB - 1) / SB) // 49 scan blocks

// ---- scratch (static device globals) ----
__device__ uint2  s_Hh[NN * 32];     // H in fp16: 128 halves = 32 uint2 per row
__device__ float4 s_P0[NN * C4];     // ping (fp32 layer output)
__device__ float4 s_P1[NN * C4];     // pong
__device__ float  s_dinv[NN];
__device__ int    s_deg [NN];
__device__ int    s_rowptr[NN + 1];
__device__ int    s_cursor[NN];
__device__ int    s_csrc [EE];
__device__ float  s_coef [EE];
__device__ int    s_bsum[64];
__device__ int    s_boff[64];

// ============ prologue ============
__global__ void zero_deg_k() {
    int i = blockIdx.x * blockDim.x + threadIdx.x;
    if (i < NN) s_deg[i] = 0;
}

__global__ void deg_k(const int* __restrict__ ei) {
    int e = blockIdx.x * blockDim.x + threadIdx.x;
    if (e < EE) {
        int dst = ei[EE + e];
        dst = min(max(dst, 0), NN - 1);
        atomicAdd(&s_deg[dst], 1);
    }
}

// hierarchical exclusive scan: phase 1 (per-block shuffle scan)
__global__ void scan1_k() {
    const int tid  = threadIdx.x;
    const int lane = tid & 31;
    const int wid  = tid >> 5;
    const int i    = blockIdx.x * SB + tid;
    int v = (i < NN) ? s_deg[i] : 0;

    int x = v;
    #pragma unroll
    for (int o = 1; o < 32; o <<= 1) {
        int t = __shfl_up_sync(0xffffffffu, x, o);
        if (lane >= o) x += t;
    }
    __shared__ int wsum[32];
    if (lane == 31) wsum[wid] = x;
    __syncthreads();
    if (wid == 0) {
        int s = wsum[lane];
        #pragma unroll
        for (int o = 1; o < 32; o <<= 1) {
            int t = __shfl_up_sync(0xffffffffu, s, o);
            if (lane >= o) s += t;
        }
        wsum[lane] = s;
    }
    __syncthreads();
    int incl = x + (wid ? wsum[wid - 1] : 0);
    if (i < NN) s_rowptr[i] = incl - v;
    if (tid == SB - 1) s_bsum[blockIdx.x] = incl;
}

// phase 2: scan block totals
__global__ void scan2_k() {
    __shared__ int sh[64];
    int t = threadIdx.x;
    int v = (t < NBK) ? s_bsum[t] : 0;
    sh[t] = v;
    __syncthreads();
    for (int o = 1; o < 64; o <<= 1) {
        int u = (t >= o) ? sh[t - o] : 0;
        __syncthreads();
        sh[t] += u;
        __syncthreads();
    }
    s_boff[t] = sh[t] - v;
}

// phase 3: apply offsets; init cursor; compute dinv
__global__ void scan3_k() {
    int i = blockIdx.x * SB + threadIdx.x;
    if (i < NN) {
        int ex = s_rowptr[i] + s_boff[blockIdx.x];
        s_rowptr[i] = ex;
        s_cursor[i] = ex;
        s_dinv[i]   = rsqrtf((float)s_deg[i] + 1.0f);
    }
    if (i == 0) s_rowptr[NN] = EE;
}

// counting-sort by dst; precompute coef
__global__ void build_k(const int* __restrict__ ei) {
    int e = blockIdx.x * blockDim.x + threadIdx.x;
    if (e >= EE) return;
    int src = ei[e];
    int dst = ei[EE + e];
    src = min(max(src, 0), NN - 1);
    dst = min(max(dst, 0), NN - 1);
    int slot = atomicAdd(&s_cursor[dst], 1);
    slot = min(max(slot, 0), EE - 1);
    s_csrc[slot] = src;
    s_coef[slot] = s_dinv[src] * s_dinv[dst];
}

// ============ GEMM: H(fp16) = act(A) @ W ============
// SRC: 0 = external x (no relu), 1 = s_P0 (relu), 2 = s_P1 (relu)
template<int SRC>
__global__ void gemm_k(const float* __restrict__ Aext, const float* __restrict__ W) {
    __shared__ float sA[32 * CC];
    const float* A = (SRC == 0) ? Aext
                   : (SRC == 1) ? (const float*)s_P0 : (const float*)s_P1;
    __half* H = (__half*)s_Hh;

    const int row0 = blockIdx.x * 32;
    const int col  = threadIdx.x;

    #pragma unroll
    for (int r = 0; r < 32; r++) {
        int row = row0 + r;
        float v = (row < NN) ? A[(size_t)row * CC + col] : 0.f;
        if (SRC != 0) v = fmaxf(v, 0.f);
        sA[r * CC + col] = v;
    }
    __syncthreads();

    float acc[32];
    #pragma unroll
    for (int r = 0; r < 32; r++) acc[r] = 0.f;

    const float4* sA4 = (const float4*)sA;
    for (int k4 = 0; k4 < 32; k4++) {
        float w0 = W[(4 * k4 + 0) * CC + col];
        float w1 = W[(4 * k4 + 1) * CC + col];
        float w2 = W[(4 * k4 + 2) * CC + col];
        float w3 = W[(4 * k4 + 3) * CC + col];
        #pragma unroll
        for (int r = 0; r < 32; r++) {
            float4 a = sA4[r * 32 + k4];          // broadcast LDS.128
            acc[r] = fmaf(a.x, w0, acc[r]);
            acc[r] = fmaf(a.y, w1, acc[r]);
            acc[r] = fmaf(a.z, w2, acc[r]);
            acc[r] = fmaf(a.w, w3, acc[r]);
        }
    }

    #pragma unroll
    for (int r = 0; r < 32; r++) {
        int row = row0 + r;
        if (row < NN) H[(size_t)row * CC + col] = __float2half(acc[r]);
    }
}

// ============ aggregation (gather of fp16 H rows) ============
// OUT[i] = sum_e H[src_e]*coef_e + H[i]*dinv[i]^2 + b    (fp32 accumulate)
template<int DST>
__global__ void agg_k(const float* __restrict__ b) {
    int node = blockIdx.x * 8 + (threadIdx.x >> 5);
    int lane = threadIdx.x & 31;
    if (node >= NN) return;
    float4* OUT = (DST == 0) ? s_P0 : s_P1;

    float di = s_dinv[node];
    float sc = di * di;

    uint2 hs = s_Hh[(size_t)node * 32 + lane];
    float2 h01 = __half22float2(*(__half2*)&hs.x);
    float2 h23 = __half22float2(*(__half2*)&hs.y);
    float4 acc;
    acc.x = fmaf(h01.x, sc, b[lane * 4 + 0]);
    acc.y = fmaf(h01.y, sc, b[lane * 4 + 1]);
    acc.z = fmaf(h23.x, sc, b[lane * 4 + 2]);
    acc.w = fmaf(h23.y, sc, b[lane * 4 + 3]);

    const int beg = s_rowptr[node];
    const int end = s_rowptr[node + 1];
    int e = beg;
    for (; e + 2 <= end; e += 2) {
        int   i0 = s_csrc[e],  i1 = s_csrc[e + 1];
        float c0 = s_coef[e],  c1 = s_coef[e + 1];
        uint2 r0 = s_Hh[(size_t)i0 * 32 + lane];
        uint2 r1 = s_Hh[(size_t)i1 * 32 + lane];
        float2 a01 = __half22float2(*(__half2*)&r0.x);
        float2 a23 = __half22float2(*(__half2*)&r0.y);
        float2 b01 = __half22float2(*(__half2*)&r1.x);
        float2 b23 = __half22float2(*(__half2*)&r1.y);
        acc.x = fmaf(a01.x, c0, fmaf(b01.x, c1, acc.x));
        acc.y = fmaf(a01.y, c0, fmaf(b01.y, c1, acc.y));
        acc.z = fmaf(a23.x, c0, fmaf(b23.x, c1, acc.z));
        acc.w = fmaf(a23.y, c0, fmaf(b23.y, c1, acc.w));
    }
    if (e < end) {
        float c0 = s_coef[e];
        uint2 r0 = s_Hh[(size_t)s_csrc[e] * 32 + lane];
        float2 a01 = __half22float2(*(__half2*)&r0.x);
        float2 a23 = __half22float2(*(__half2*)&r0.y);
        acc.x = fmaf(a01.x, c0, acc.x);
        acc.y = fmaf(a01.y, c0, acc.y);
        acc.z = fmaf(a23.x, c0, acc.z);
        acc.w = fmaf(a23.y, c0, acc.w);
    }
    OUT[(size_t)node * C4 + lane] = acc;
}

// ============ fused mean-pool (batch sorted int32) + FC ============
__global__ void poolfc_k(const int* __restrict__ batch,
                         const float* __restrict__ Wfc,
                         const float* __restrict__ bfc,
                         float* __restrict__ out) {
    int g = blockIdx.x;
    int t = threadIdx.x;
    __shared__ int sb[2];
    if (t < 2) {
        int key = g + t;
        int lo = 0, hi = NN;
        while (lo < hi) {
            int mid = (lo + hi) >> 1;
            if (batch[mid] < key) lo = mid + 1; else hi = mid;
        }
        sb[t] = lo;
    }
    __syncthreads();
    const int beg = sb[0], end = sb[1];

    const float* A = (const float*)s_P1;
    float s = 0.f;
    for (int r = beg; r < end; r++)
        s += fmaxf(A[(size_t)r * CC + t], 0.f);

    float v = s * Wfc[t];
    #pragma unroll
    for (int o = 16; o; o >>= 1) v += __shfl_xor_sync(0xffffffffu, v, o);
    __shared__ float sred[4];
    if ((t & 31) == 0) sred[t >> 5] = v;
    __syncthreads();
    if (t == 0) {
        float total = sred[0] + sred[1] + sred[2] + sred[3];
        out[g] = total / fmaxf((float)(end - beg), 1.0f) + bfc[0];
    }
}

extern "C" void kernel_launch(void* const* d_in, const int* in_sizes, int n_in,
                              void* d_out, int out_size) {
    const float* x   = (const float*)d_in[0];
    const int*   ei  = (const int*)d_in[1];    // int32 [2, E]
    const int*   bat = (const int*)d_in[2];    // int32 [N]
    const float* W1  = (const float*)d_in[3];
    const float* b1  = (const float*)d_in[4];
    const float* W2  = (const float*)d_in[5];
    const float* b2  = (const float*)d_in[6];
    const float* Wfc = (const float*)d_in[7];
    const float* bfc = (const float*)d_in[8];
    float*       out = (float*)d_out;

    const int T = 256;
    const int NB_N = (NN + T - 1) / T;
    const int NB_E = (EE + T - 1) / T;
    const int GB   = (NN + 31) / 32;
    const int AB   = (NN + 7) / 8;

    // prologue: CSR build
    zero_deg_k<<<NB_N, T>>>();
    deg_k     <<<NB_E, T>>>(ei);
    scan1_k   <<<NBK, SB>>>();
    scan2_k   <<<1, 64>>>();
    scan3_k   <<<NBK, SB>>>();
    build_k   <<<NB_E, T>>>(ei);

    // 4 GCN layers: gemm(fp32 acc, fp16 H out) -> gather-agg(fp32 acc)
    gemm_k<0><<<GB, CC>>>(x, W1);  agg_k<0><<<AB, T>>>(b1);   // x  -> P0
    gemm_k<1><<<GB, CC>>>(x, W2);  agg_k<1><<<AB, T>>>(b2);   // P0 -> P1
    gemm_k<2><<<GB, CC>>>(x, W2);  agg_k<0><<<AB, T>>>(b2);   // P1 -> P0
    gemm_k<1><<<GB, CC>>>(x, W2);  agg_k<1><<<AB, T>>>(b2);   // P0 -> P1

    // pool (relu fused) + fc
    poolfc_k<<<NG, CC>>>(bat, Wfc, bfc, out);
}

// round 9
// speedup vs baseline: 1.9905x; 1.6432x over previous
#include <cuda_runtime.h>
#include <cuda_fp16.h>
#include <cstdint>

#define NN 50000
#define EE 1600000
#define CC 128
#define NG 128
#define SB 1024
#define NBK ((NN + SB - 1) / SB)

// ---- scratch (static device globals) ----
__device__ uint2  s_Hh [NN * 32];    // H  fp16: 128 halves/row
__device__ uint2  s_P0h[NN * 32];    // layer out fp16 (relu applied)
__device__ uint2  s_P1h[NN * 32];
__device__ __half s_W1h[CC * CC];
__device__ __half s_W2h[CC * CC];
__device__ float  s_dinv[NN];
__device__ int    s_deg [NN];
__device__ int    s_rowptr[NN + 1];
__device__ int    s_cursor[NN];
__device__ int    s_csrc [EE];
__device__ float  s_coef [EE];
__device__ int    s_bsum[64];
__device__ int    s_boff[64];

// ============ prologue ============
__global__ void zero_deg_k() {
    int i = blockIdx.x * blockDim.x + threadIdx.x;
    if (i < NN) s_deg[i] = 0;
}

__global__ void deg_k(const int* __restrict__ ei) {
    int e = blockIdx.x * blockDim.x + threadIdx.x;
    if (e < EE) {
        int dst = ei[EE + e];
        dst = min(max(dst, 0), NN - 1);
        atomicAdd(&s_deg[dst], 1);
    }
}

__global__ void scan1_k() {
    const int tid  = threadIdx.x;
    const int lane = tid & 31;
    const int wid  = tid >> 5;
    const int i    = blockIdx.x * SB + tid;
    int v = (i < NN) ? s_deg[i] : 0;
    int x = v;
    #pragma unroll
    for (int o = 1; o < 32; o <<= 1) {
        int t = __shfl_up_sync(0xffffffffu, x, o);
        if (lane >= o) x += t;
    }
    __shared__ int wsum[32];
    if (lane == 31) wsum[wid] = x;
    __syncthreads();
    if (wid == 0) {
        int s = wsum[lane];
        #pragma unroll
        for (int o = 1; o < 32; o <<= 1) {
            int t = __shfl_up_sync(0xffffffffu, s, o);
            if (lane >= o) s += t;
        }
        wsum[lane] = s;
    }
    __syncthreads();
    int incl = x + (wid ? wsum[wid - 1] : 0);
    if (i < NN) s_rowptr[i] = incl - v;
    if (tid == SB - 1) s_bsum[blockIdx.x] = incl;
}

__global__ void scan2_k() {
    __shared__ int sh[64];
    int t = threadIdx.x;
    int v = (t < NBK) ? s_bsum[t] : 0;
    sh[t] = v;
    __syncthreads();
    for (int o = 1; o < 64; o <<= 1) {
        int u = (t >= o) ? sh[t - o] : 0;
        __syncthreads();
        sh[t] += u;
        __syncthreads();
    }
    s_boff[t] = sh[t] - v;
}

__global__ void scan3_k() {
    int i = blockIdx.x * SB + threadIdx.x;
    if (i < NN) {
        int ex = s_rowptr[i] + s_boff[blockIdx.x];
        s_rowptr[i] = ex;
        s_cursor[i] = ex;
        s_dinv[i]   = rsqrtf((float)s_deg[i] + 1.0f);
    }
    if (i == 0) s_rowptr[NN] = EE;
}

__global__ void build_k(const int* __restrict__ ei) {
    int e = blockIdx.x * blockDim.x + threadIdx.x;
    if (e >= EE) return;
    int src = ei[e];
    int dst = ei[EE + e];
    src = min(max(src, 0), NN - 1);
    dst = min(max(dst, 0), NN - 1);
    int slot = atomicAdd(&s_cursor[dst], 1);
    slot = min(max(slot, 0), EE - 1);
    s_csrc[slot] = src;
    s_coef[slot] = s_dinv[src] * s_dinv[dst];
}

// convert both weight matrices to fp16 once
__global__ void wconv_k(const float* __restrict__ W1, const float* __restrict__ W2) {
    int i = blockIdx.x * blockDim.x + threadIdx.x;
    if (i < CC * CC) {
        s_W1h[i] = __float2half(W1[i]);
        s_W2h[i] = __float2half(W2[i]);
    }
}

// ============ tensor-core GEMM: H(fp16) = A @ W ============
// block tile 64 rows x 128 cols, 256 threads (8 warps: 4m x 2n),
// warp tile 16 x 64 = 1 m-tile x 8 n-tiles of m16n8k16.
// SRC: 0 = external x (fp32, no relu), 1 = s_P0h, 2 = s_P1h (fp16, pre-relu'd)
__device__ __forceinline__ unsigned swz(unsigned row, unsigned col_half) {
    unsigned b = row * 256u + col_half * 2u;
    return b ^ ((row & 7u) << 4);
}

template<int SRC>
__global__ void __launch_bounds__(256) gemm_tc_k(const float* __restrict__ X,
                                                 const __half* __restrict__ Wh) {
    __shared__ __align__(16) unsigned char smem[49152];   // A: 16KB, W: 32KB
    const unsigned sb  = (unsigned)__cvta_generic_to_shared(smem);
    const unsigned sbA = sb;
    const unsigned sbW = sb + 16384u;
    const int tid  = threadIdx.x;
    const int row0 = blockIdx.x * 64;

    // ---- load A tile (64 x 128) into swizzled fp16 smem ----
    if (SRC == 0) {
        #pragma unroll
        for (int it = 0; it < 4; it++) {
            int idx = it * 256 + tid;             // 1024 16B-chunks
            int r   = idx >> 4;
            int c16 = idx & 15;                   // chunk of 8 halves
            int gr  = row0 + r;
            uint4 o;
            if (gr < NN) {
                const float4* p = (const float4*)(X + (size_t)gr * CC + c16 * 8);
                float4 f0 = p[0], f1 = p[1];
                __half2 h0 = __floats2half2_rn(f0.x, f0.y);
                __half2 h1 = __floats2half2_rn(f0.z, f0.w);
                __half2 h2 = __floats2half2_rn(f1.x, f1.y);
                __half2 h3 = __floats2half2_rn(f1.z, f1.w);
                o.x = *(unsigned*)&h0; o.y = *(unsigned*)&h1;
                o.z = *(unsigned*)&h2; o.w = *(unsigned*)&h3;
            } else {
                o = make_uint4(0u, 0u, 0u, 0u);
            }
            *(uint4*)(smem + swz((unsigned)r, (unsigned)(c16 * 8))) = o;
        }
    } else {
        const __half* P = (SRC == 1) ? (const __half*)s_P0h : (const __half*)s_P1h;
        #pragma unroll
        for (int it = 0; it < 4; it++) {
            int idx = it * 256 + tid;
            int r   = idx >> 4;
            int c16 = idx & 15;
            int gr  = row0 + r;
            uint4 o = make_uint4(0u, 0u, 0u, 0u);
            if (gr < NN) o = *(const uint4*)(P + (size_t)gr * CC + c16 * 8);
            *(uint4*)(smem + swz((unsigned)r, (unsigned)(c16 * 8))) = o;
        }
    }
    // ---- load W (128 x 128 fp16) into swizzled smem ----
    #pragma unroll
    for (int it = 0; it < 8; it++) {
        int idx = it * 256 + tid;                 // 2048 chunks
        int r   = idx >> 4;
        int c16 = idx & 15;
        uint4 o = *(const uint4*)(Wh + (size_t)r * CC + c16 * 8);
        *(uint4*)(smem + 16384 + swz((unsigned)r, (unsigned)(c16 * 8))) = o;
    }
    __syncthreads();

    const int warp   = tid >> 5;
    const int lane   = tid & 31;
    const int warp_m = warp & 3;                  // 0..3 -> rows 16*wm
    const int warp_n = warp >> 2;                 // 0..1 -> cols 64*wn
    const int rloc   = warp_m * 16;
    const int c0     = warp_n * 64;

    float d[8][4];
    #pragma unroll
    for (int i = 0; i < 8; i++)
        #pragma unroll
        for (int j = 0; j < 4; j++) d[i][j] = 0.f;

    const int fr = (lane & 7) + ((lane >> 3) & 1) * 8;   // fragment row
    const int fc = (lane >> 4) * 8;                      // fragment col (halves)

    #pragma unroll
    for (int ks = 0; ks < 8; ks++) {
        const int k0 = ks * 16;
        unsigned a0, a1, a2, a3;
        {
            unsigned addrA = sbA + swz((unsigned)(rloc + fr), (unsigned)(k0 + fc));
            asm volatile("ldmatrix.sync.aligned.m8n8.x4.shared.b16 {%0,%1,%2,%3}, [%4];"
                         : "=r"(a0), "=r"(a1), "=r"(a2), "=r"(a3) : "r"(addrA));
        }
        #pragma unroll
        for (int q = 0; q < 4; q++) {              // 2 n-tiles per ldmatrix.x4
            int n0 = c0 + q * 16;
            unsigned b0, b1, b2, b3;
            unsigned addrB = sbW + swz((unsigned)(k0 + fr), (unsigned)(n0 + fc));
            asm volatile("ldmatrix.sync.aligned.m8n8.x4.trans.shared.b16 {%0,%1,%2,%3}, [%4];"
                         : "=r"(b0), "=r"(b1), "=r"(b2), "=r"(b3) : "r"(addrB));
            asm volatile("mma.sync.aligned.m16n8k16.row.col.f32.f16.f16.f32 "
                         "{%0,%1,%2,%3}, {%4,%5,%6,%7}, {%8,%9}, {%0,%1,%2,%3};"
                         : "+f"(d[q*2][0]), "+f"(d[q*2][1]), "+f"(d[q*2][2]), "+f"(d[q*2][3])
                         : "r"(a0), "r"(a1), "r"(a2), "r"(a3), "r"(b0), "r"(b1));
            asm volatile("mma.sync.aligned.m16n8k16.row.col.f32.f16.f16.f32 "
                         "{%0,%1,%2,%3}, {%4,%5,%6,%7}, {%8,%9}, {%0,%1,%2,%3};"
                         : "+f"(d[q*2+1][0]), "+f"(d[q*2+1][1]), "+f"(d[q*2+1][2]), "+f"(d[q*2+1][3])
                         : "r"(a0), "r"(a1), "r"(a2), "r"(a3), "r"(b2), "r"(b3));
        }
    }

    // ---- epilogue: write H fp16 ----
    __half* H = (__half*)s_Hh;
    const int g  = lane >> 2;
    const int cq = (lane & 3) * 2;
    const int ra = row0 + rloc + g;
    const int rb = ra + 8;
    #pragma unroll
    for (int nt = 0; nt < 8; nt++) {
        int col = c0 + nt * 8 + cq;
        if (ra < NN) *(__half2*)(H + (size_t)ra * CC + col) = __floats2half2_rn(d[nt][0], d[nt][1]);
        if (rb < NN) *(__half2*)(H + (size_t)rb * CC + col) = __floats2half2_rn(d[nt][2], d[nt][3]);
    }
}

// ============ aggregation: gather fp16, fp32 acc, relu, write fp16 ============
// OUT[i] = relu( sum_e H[src]*coef + H[i]*dinv^2 + b )
template<int DST>
__global__ void agg_k(const float* __restrict__ b) {
    int node = blockIdx.x * 8 + (threadIdx.x >> 5);
    int lane = threadIdx.x & 31;
    if (node >= NN) return;
    uint2* OUT = (DST == 0) ? s_P0h : s_P1h;

    float di = s_dinv[node];
    float sc = di * di;

    uint2 hs = s_Hh[(size_t)node * 32 + lane];
    float2 h01 = __half22float2(*(__half2*)&hs.x);
    float2 h23 = __half22float2(*(__half2*)&hs.y);
    float4 acc;
    acc.x = fmaf(h01.x, sc, b[lane * 4 + 0]);
    acc.y = fmaf(h01.y, sc, b[lane * 4 + 1]);
    acc.z = fmaf(h23.x, sc, b[lane * 4 + 2]);
    acc.w = fmaf(h23.y, sc, b[lane * 4 + 3]);

    const int beg = s_rowptr[node];
    const int end = s_rowptr[node + 1];
    int e = beg;
    for (; e + 4 <= end; e += 4) {
        int   i0 = s_csrc[e],   i1 = s_csrc[e+1], i2 = s_csrc[e+2], i3 = s_csrc[e+3];
        float c0 = s_coef[e],   c1 = s_coef[e+1], c2 = s_coef[e+2], c3 = s_coef[e+3];
        uint2 r0 = s_Hh[(size_t)i0 * 32 + lane];
        uint2 r1 = s_Hh[(size_t)i1 * 32 + lane];
        uint2 r2 = s_Hh[(size_t)i2 * 32 + lane];
        uint2 r3 = s_Hh[(size_t)i3 * 32 + lane];
        float2 a01, a23;
        a01 = __half22float2(*(__half2*)&r0.x); a23 = __half22float2(*(__half2*)&r0.y);
        acc.x = fmaf(a01.x, c0, acc.x); acc.y = fmaf(a01.y, c0, acc.y);
        acc.z = fmaf(a23.x, c0, acc.z); acc.w = fmaf(a23.y, c0, acc.w);
        a01 = __half22float2(*(__half2*)&r1.x); a23 = __half22float2(*(__half2*)&r1.y);
        acc.x = fmaf(a01.x, c1, acc.x); acc.y = fmaf(a01.y, c1, acc.y);
        acc.z = fmaf(a23.x, c1, acc.z); acc.w = fmaf(a23.y, c1, acc.w);
        a01 = __half22float2(*(__half2*)&r2.x); a23 = __half22float2(*(__half2*)&r2.y);
        acc.x = fmaf(a01.x, c2, acc.x); acc.y = fmaf(a01.y, c2, acc.y);
        acc.z = fmaf(a23.x, c2, acc.z); acc.w = fmaf(a23.y, c2, acc.w);
        a01 = __half22float2(*(__half2*)&r3.x); a23 = __half22float2(*(__half2*)&r3.y);
        acc.x = fmaf(a01.x, c3, acc.x); acc.y = fmaf(a01.y, c3, acc.y);
        acc.z = fmaf(a23.x, c3, acc.z); acc.w = fmaf(a23.y, c3, acc.w);
    }
    for (; e < end; e++) {
        float c0 = s_coef[e];
        uint2 r0 = s_Hh[(size_t)s_csrc[e] * 32 + lane];
        float2 a01 = __half22float2(*(__half2*)&r0.x);
        float2 a23 = __half22float2(*(__half2*)&r0.y);
        acc.x = fmaf(a01.x, c0, acc.x); acc.y = fmaf(a01.y, c0, acc.y);
        acc.z = fmaf(a23.x, c0, acc.z); acc.w = fmaf(a23.y, c0, acc.w);
    }

    // relu + pack fp16
    __half2 o0 = __floats2half2_rn(fmaxf(acc.x, 0.f), fmaxf(acc.y, 0.f));
    __half2 o1 = __floats2half2_rn(fmaxf(acc.z, 0.f), fmaxf(acc.w, 0.f));
    uint2 o;
    o.x = *(unsigned*)&o0;
    o.y = *(unsigned*)&o1;
    OUT[(size_t)node * 32 + lane] = o;
}

// ============ mean-pool (batch sorted) + FC; input fp16 already relu'd ============
__global__ void poolfc_k(const int* __restrict__ batch,
                         const float* __restrict__ Wfc,
                         const float* __restrict__ bfc,
                         float* __restrict__ out) {
    int g = blockIdx.x;
    int t = threadIdx.x;
    __shared__ int sb2[2];
    if (t < 2) {
        int key = g + t;
        int lo = 0, hi = NN;
        while (lo < hi) {
            int mid = (lo + hi) >> 1;
            if (batch[mid] < key) lo = mid + 1; else hi = mid;
        }
        sb2[t] = lo;
    }
    __syncthreads();
    const int beg = sb2[0], end = sb2[1];

    const __half* A = (const __half*)s_P1h;
    float s = 0.f;
    for (int r = beg; r < end; r++)
        s += __half2float(A[(size_t)r * CC + t]);

    float v = s * Wfc[t];
    #pragma unroll
    for (int o = 16; o; o >>= 1) v += __shfl_xor_sync(0xffffffffu, v, o);
    __shared__ float sred[4];
    if ((t & 31) == 0) sred[t >> 5] = v;
    __syncthreads();
    if (t == 0) {
        float total = sred[0] + sred[1] + sred[2] + sred[3];
        out[g] = total / fmaxf((float)(end - beg), 1.0f) + bfc[0];
    }
}

extern "C" void kernel_launch(void* const* d_in, const int* in_sizes, int n_in,
                              void* d_out, int out_size) {
    const float* x   = (const float*)d_in[0];
    const int*   ei  = (const int*)d_in[1];    // int32 [2, E]
    const int*   bat = (const int*)d_in[2];    // int32 [N]
    const float* W1  = (const float*)d_in[3];
    const float* b1  = (const float*)d_in[4];
    const float* W2  = (const float*)d_in[5];
    const float* b2  = (const float*)d_in[6];
    const float* Wfc = (const float*)d_in[7];
    const float* bfc = (const float*)d_in[8];
    float*       out = (float*)d_out;

    __half *W1h, *W2h;
    cudaGetSymbolAddress((void**)&W1h, s_W1h);
    cudaGetSymbolAddress((void**)&W2h, s_W2h);

    const int T = 256;
    const int NB_N = (NN + T - 1) / T;
    const int NB_E = (EE + T - 1) / T;
    const int GB   = (NN + 63) / 64;
    const int AB   = (NN + 7) / 8;

    // prologue: CSR build + weight conversion
    zero_deg_k<<<NB_N, T>>>();
    deg_k     <<<NB_E, T>>>(ei);
    scan1_k   <<<NBK, SB>>>();
    scan2_k   <<<1, 64>>>();
    scan3_k   <<<NBK, SB>>>();
    build_k   <<<NB_E, T>>>(ei);
    wconv_k   <<<(CC * CC + T - 1) / T, T>>>(W1, W2);

    // 4 GCN layers
    gemm_tc_k<0><<<GB, 256>>>(x, W1h);  agg_k<0><<<AB, T>>>(b1);   // x   -> P0h
    gemm_tc_k<1><<<GB, 256>>>(x, W2h);  agg_k<1><<<AB, T>>>(b2);   // P0h -> P1h
    gemm_tc_k<2><<<GB, 256>>>(x, W2h);  agg_k<0><<<AB, T>>>(b2);   // P1h -> P0h
    gemm_tc_k<1><<<GB, 256>>>(x, W2h);  agg_k<1><<<AB, T>>>(b2);   // P0h -> P1h

    // pool + fc
    poolfc_k<<<NG, CC>>>(bat, Wfc, bfc, out);
}